// round 5
// baseline (speedup 1.0000x reference)
#include <cuda_runtime.h>
#include <cuda_bf16.h>
#include <cstdint>
#include <cstddef>

#define BB 16
#define IC 8
#define OC 8
#define NV 3
#define HH 256
#define WW 256
#define M1 16
#define M2 16
#define TD 256

// -------------------- static scratch (no runtime allocation) --------------------
__device__ __align__(16) float2 g_Y[BB*IC*NV*HH*16];      // fwd DFT over w
__device__ __align__(16) float2 g_X[BB*IC*NV*32*16];      // fwd modes
__device__ __align__(16) float  g_TW[4*BB*(IC*OC*NV*M1*M2)]; // time-contracted weights
__device__ __align__(16) float2 g_G[BB*OC*NV*32*16];      // mixed modes
__device__ __align__(16) float2 g_Z[BB*OC*NV*HH*16];      // inv DFT over h
// twiddle tables (computed by k0 each launch)
__device__ __align__(16) float2 g_T1[2048];               // [w][k]: (cos, -sin)(2pi k w/256)
__device__ __align__(16) float  g_T5c[2048];              // [kw][w]: cos * al
__device__ __align__(16) float  g_T5s[2048];              // [kw][w]: sin * al

// ---------------------------------------------------------------------------
// k0: compute twiddle tables once per launch. 8 x 256 threads.
// ---------------------------------------------------------------------------
__global__ __launch_bounds__(256) void k0_tables() {
    const int idx = blockIdx.x * 256 + threadIdx.x;    // 0..2047
    // k5 table: layout [kw][w], scale folded
    {
        int kw = idx >> 7, w = idx & 127;
        float sn, cs;
        sincospif((float)(kw * w) * (1.0f / 128.0f), &sn, &cs);
        float al = ((kw == 0) ? 1.0f : 2.0f) * (1.0f / 65536.0f);
        g_T5c[idx] = cs * al;
        g_T5s[idx] = sn * al;
    }
    // k1 table: layout [w][k], value e^{-2pi i k w/256}
    {
        int w = idx >> 4, k = idx & 15;
        float sn, cs;
        sincospif((float)(k * w) * (1.0f / 128.0f), &sn, &cs);
        g_T1[idx] = make_float2(cs, -sn);
    }
}

// ---------------------------------------------------------------------------
// k1: forward DFT over w, modes kw=0..15. Parity split over w.
// Table twiddles from g_T1 staged to smem ([w][k] layout, conflict-free).
// Block: 128 threads = 16 modes x 8 row-groups; 16 rows/block (2 rows per
// thread: rg and rg+8). smem = 16KB data + 16KB table = 32KB. Grid: 6144.
// ---------------------------------------------------------------------------
__global__ __launch_bounds__(128) void k1_fwd_w(const float* __restrict__ x) {
    __shared__ float sx[16][256];
    __shared__ float2 stw[2048];   // [w][k]
    const int tid = threadIdx.x;

    const float4* xg = (const float4*)(x + (size_t)blockIdx.x * (16 * 256));
    float4* sx4 = (float4*)sx;
#pragma unroll
    for (int it = 0; it < 8; it++)
        sx4[it * 128 + tid] = xg[it * 128 + tid];
    float4* stw4 = (float4*)stw;
    const float4* gt4 = (const float4*)g_T1;
#pragma unroll
    for (int j = 0; j < 8; j++)
        stw4[j * 128 + tid] = gt4[j * 128 + tid];
    __syncthreads();

    // parity: sum in cols [0,128), diff in [128,256)
#pragma unroll
    for (int p = tid; p < 2048; p += 128) {
        int r = p >> 7, w = p & 127;
        float a = sx[r][w], b = sx[r][w + 128];
        sx[r][w]       = a + b;
        sx[r][w + 128] = a - b;
    }
    __syncthreads();

    const int k  = tid & 15;
    const int rg = tid >> 4;           // 0..7 -> rows rg, rg+8
    const int base = (k & 1) << 7;

    float ar0 = 0, ai0 = 0, ar1 = 0, ai1 = 0;
#pragma unroll 4
    for (int w4 = 0; w4 < 32; w4++) {
        float4 v0 = *(const float4*)&sx[rg    ][base + w4 * 4];
        float4 v1 = *(const float4*)&sx[rg + 8][base + w4 * 4];
        float e0[4] = {v0.x, v0.y, v0.z, v0.w};
        float e1[4] = {v1.x, v1.y, v1.z, v1.w};
#pragma unroll
        for (int u = 0; u < 4; u++) {
            float2 tw = stw[(w4 * 4 + u) * 16 + k];
            ar0 += e0[u] * tw.x; ai0 += e0[u] * tw.y;
            ar1 += e1[u] * tw.x; ai1 += e1[u] * tw.y;
        }
    }

    size_t rowbase = (size_t)blockIdx.x * 16;
    g_Y[(rowbase + rg    ) * 16 + k] = make_float2(ar0, ai0);
    g_Y[(rowbase + rg + 8) * 16 + k] = make_float2(ar1, ai1);
}

// ---------------------------------------------------------------------------
// k2: forward DFT over h for kh in {0..15} U {240..255}. One block per (b,i,v).
// Grid: 384, 256 threads. Incremental phasor rotation (2 sincospif/thread).
// ---------------------------------------------------------------------------
__global__ __launch_bounds__(256) void k2_fwd_h() {
    __shared__ float2 sy[4096];   // [h][kw]
    const int tid = threadIdx.x;

    const float4* yg = (const float4*)(g_Y + (size_t)blockIdx.x * 4096);
    float4* sy4 = (float4*)sy;
#pragma unroll
    for (int it = 0; it < 8; it++)
        sy4[it * 256 + tid] = yg[it * 256 + tid];
    __syncthreads();

#pragma unroll
    for (int p = tid; p < 2048; p += 256) {
        int h = p >> 4, kw = p & 15;
        float2 a = sy[h * 16 + kw], b = sy[(h + 128) * 16 + kw];
        sy[h * 16 + kw]         = make_float2(a.x + b.x, a.y + b.y);
        sy[(h + 128) * 16 + kw] = make_float2(a.x - b.x, a.y - b.y);
    }
    __syncthreads();

    const int kw = tid & 15;
    const int s  = tid >> 4;
    const int hbase = (s & 1) << 7;

    float s1, c1, s2, c2;
    sincospif((float)s * (1.0f / 128.0f), &s1, &c1);
    sincospif((float)(s - 16) * (1.0f / 128.0f), &s2, &c2);
    const float st1c = c1, st1s = -s1;
    const float st2c = c2, st2s = -s2;
    float p1c = 1, p1s = 0, p2c = 1, p2s = 0;
    float a1r = 0, a1i = 0, a2r = 0, a2i = 0;

#pragma unroll 4
    for (int h = 0; h < 128; h++) {
        float2 u = sy[(hbase + h) * 16 + kw];
        a1r += u.x * p1c - u.y * p1s;
        a1i += u.x * p1s + u.y * p1c;
        a2r += u.x * p2c - u.y * p2s;
        a2i += u.x * p2s + u.y * p2c;
        float n;
        n = p1c * st1c - p1s * st1s; p1s = p1c * st1s + p1s * st1c; p1c = n;
        n = p2c * st2c - p2s * st2s; p2s = p2c * st2s + p2s * st2c; p2c = n;
    }

    size_t ob = (size_t)blockIdx.x * 512;
    g_X[ob + s * 16 + kw]        = make_float2(a1r, a1i);
    g_X[ob + (16 + s) * 16 + kw] = make_float2(a2r, a2i);
}

// ---------------------------------------------------------------------------
// k3a: time contraction TW[arr][b][row] = sum_t t[b,t] * W[row, t]
// Block: 128 threads, 4 rows/thread. Grid: (96, 4).
// ---------------------------------------------------------------------------
__global__ __launch_bounds__(128) void k3a_time(const float* __restrict__ t,
                                                const float* __restrict__ wa,
                                                const float* __restrict__ wb,
                                                const float* __restrict__ wc,
                                                const float* __restrict__ wd) {
    __shared__ float ts[256][16];
    const int tid = threadIdx.x;
#pragma unroll
    for (int j = tid; j < 4096; j += 128) {
        int b = j & 15, k = j >> 4;
        ts[k][b] = t[b * 256 + k];
    }
    __syncthreads();

    const float* W = (blockIdx.y == 0) ? wa : (blockIdx.y == 1) ? wb
                   : (blockIdx.y == 2) ? wc : wd;
    float* out = g_TW + (size_t)blockIdx.y * (16 * 49152);

    const int row0 = blockIdx.x * 512 + tid * 4;
    float acc[4][16];
#pragma unroll
    for (int r = 0; r < 4; r++)
#pragma unroll
        for (int b = 0; b < 16; b++) acc[r][b] = 0.0f;

    const float4* Wp = (const float4*)(W + (size_t)row0 * 256);

    for (int k4 = 0; k4 < 64; k4++) {
        float4 wv0 = Wp[k4];
        float4 wv1 = Wp[64 + k4];
        float4 wv2 = Wp[128 + k4];
        float4 wv3 = Wp[192 + k4];
#pragma unroll
        for (int kk = 0; kk < 4; kk++) {
            const float4* trp = (const float4*)&ts[k4 * 4 + kk][0];
            float4 ta = trp[0], tb = trp[1], tc = trp[2], td = trp[3];
            float wf[4];
            wf[0] = (kk == 0) ? wv0.x : (kk == 1) ? wv0.y : (kk == 2) ? wv0.z : wv0.w;
            wf[1] = (kk == 0) ? wv1.x : (kk == 1) ? wv1.y : (kk == 2) ? wv1.z : wv1.w;
            wf[2] = (kk == 0) ? wv2.x : (kk == 1) ? wv2.y : (kk == 2) ? wv2.z : wv2.w;
            wf[3] = (kk == 0) ? wv3.x : (kk == 1) ? wv3.y : (kk == 2) ? wv3.z : wv3.w;
#pragma unroll
            for (int r = 0; r < 4; r++) {
                acc[r][0]  += wf[r] * ta.x; acc[r][1]  += wf[r] * ta.y;
                acc[r][2]  += wf[r] * ta.z; acc[r][3]  += wf[r] * ta.w;
                acc[r][4]  += wf[r] * tb.x; acc[r][5]  += wf[r] * tb.y;
                acc[r][6]  += wf[r] * tb.z; acc[r][7]  += wf[r] * tb.w;
                acc[r][8]  += wf[r] * tc.x; acc[r][9]  += wf[r] * tc.y;
                acc[r][10] += wf[r] * tc.z; acc[r][11] += wf[r] * tc.w;
                acc[r][12] += wf[r] * td.x; acc[r][13] += wf[r] * td.y;
                acc[r][14] += wf[r] * td.z; acc[r][15] += wf[r] * td.w;
            }
        }
    }

#pragma unroll
    for (int b = 0; b < 16; b++) {
        float4 v = make_float4(acc[0][b], acc[1][b], acc[2][b], acc[3][b]);
        *(float4*)&out[(size_t)b * 49152 + row0] = v;
    }
}

// ---------------------------------------------------------------------------
// k3b: spectral mixing over IC. Grid: 768 x 256.
// ---------------------------------------------------------------------------
__global__ __launch_bounds__(256) void k3b_mix() {
    const int gtid = blockIdx.x * 256 + threadIdx.x;
    const int kw = gtid & 15;
    int r = gtid >> 4;
    const int s = r & 31; r >>= 5;
    const int v = r % 3;  r /= 3;
    const int o = r & 7;
    const int b = r >> 3;

    const int arrbase = (s < 16) ? 0 : 2;
    const int y = s & 15;
    const float* TR = g_TW + (size_t)(arrbase * 16 + b) * 49152;
    const float* TI = g_TW + (size_t)((arrbase + 1) * 16 + b) * 49152;

    float gr = 0.0f, gi = 0.0f;
#pragma unroll
    for (int i = 0; i < 8; i++) {
        float2 xf = g_X[((size_t)((b * 8 + i) * 3 + v) * 32 + s) * 16 + kw];
        int row = (((i * 8 + o) * 3 + v) * 16 + y) * 16 + kw;
        float wr = TR[row], wi = TI[row];
        gr += xf.x * wr - xf.y * wi;
        gi += xf.x * wi + xf.y * wr;
    }
    g_G[gtid] = make_float2(gr, gi);
}

// ---------------------------------------------------------------------------
// k4: inverse DFT over h, parity split: thread h (0..127) produces h and h+128.
// Even-kh slots accumulate into A, odd into B; Z[h]=A+B, Z[h+128]=A-B.
// Phasor rotation: 1 sincospif/thread, conj jump at the kh=240 boundary.
// Grid: 384 x 128.
// ---------------------------------------------------------------------------
__global__ __launch_bounds__(128) void k4_inv_h() {
    __shared__ float2 Gs[512];
    const int tid = threadIdx.x;
    {
        float4* g4 = (float4*)Gs;
        const float4* s4 = (const float4*)(g_G + (size_t)blockIdx.x * 512);
        g4[tid] = s4[tid];
        g4[tid + 128] = s4[tid + 128];
    }
    __syncthreads();

    const int h = tid;   // 0..127
    float AR[16], AI[16], BR[16], BI[16];
#pragma unroll
    for (int q = 0; q < 16; q++) { AR[q] = AI[q] = BR[q] = BI[q] = 0.0f; }

    float stc, sts;
    sincospif((float)h * (1.0f / 128.0f), &sts, &stc);   // step = e^{+2pi i h/256}
    float pc = 1.0f, ps = 0.0f;

#pragma unroll 1
    for (int sl = 0; sl < 32; sl++) {
        if (sl == 16) { ps = -ps; }   // p = e^{i16h} -> conj -> e^{-i16h} (kh=240)
        const float4* gp = (const float4*)&Gs[sl * 16];
        if ((sl & 1) == 0) {
#pragma unroll
            for (int q4 = 0; q4 < 8; q4++) {
                float4 g = gp[q4];
                AR[2*q4]   += g.x * pc - g.y * ps;
                AI[2*q4]   += g.x * ps + g.y * pc;
                AR[2*q4+1] += g.z * pc - g.w * ps;
                AI[2*q4+1] += g.z * ps + g.w * pc;
            }
        } else {
#pragma unroll
            for (int q4 = 0; q4 < 8; q4++) {
                float4 g = gp[q4];
                BR[2*q4]   += g.x * pc - g.y * ps;
                BI[2*q4]   += g.x * ps + g.y * pc;
                BR[2*q4+1] += g.z * pc - g.w * ps;
                BI[2*q4+1] += g.z * ps + g.w * pc;
            }
        }
        float n = pc * stc - ps * sts;
        ps = pc * sts + ps * stc; pc = n;
    }

    float4* zlo = (float4*)(g_Z + (size_t)blockIdx.x * 4096 + h * 16);
    float4* zhi = (float4*)(g_Z + (size_t)blockIdx.x * 4096 + (h + 128) * 16);
#pragma unroll
    for (int q = 0; q < 8; q++) {
        zlo[q] = make_float4(AR[2*q] + BR[2*q], AI[2*q] + BI[2*q],
                             AR[2*q+1] + BR[2*q+1], AI[2*q+1] + BI[2*q+1]);
        zhi[q] = make_float4(AR[2*q] - BR[2*q], AI[2*q] - BI[2*q],
                             AR[2*q+1] - BR[2*q+1], AI[2*q+1] - BI[2*q+1]);
    }
}

// ---------------------------------------------------------------------------
// k5: inverse real DFT over w, parity split. Tables staged from global.
// Block: 32 rows, 256 threads. Grid: 3072.
// ---------------------------------------------------------------------------
__global__ __launch_bounds__(256) void k5_inv_w(float* __restrict__ out) {
    __shared__ float Ct[16 * 128];
    __shared__ float St[16 * 128];
    __shared__ float2 Zs[512];
    const int tid = threadIdx.x;

    {
        float4* c4 = (float4*)Ct; const float4* gc = (const float4*)g_T5c;
        float4* s4 = (float4*)St; const float4* gs = (const float4*)g_T5s;
#pragma unroll
        for (int j = 0; j < 2; j++) {
            c4[j * 256 + tid] = gc[j * 256 + tid];
            s4[j * 256 + tid] = gs[j * 256 + tid];
        }
    }
    ((float4*)Zs)[tid] = ((const float4*)(g_Z + (size_t)blockIdx.x * 512))[tid];
    __syncthreads();

    const int r  = tid >> 3;
    const int wb = tid & 7;

    float A[16], B[16];
#pragma unroll
    for (int u = 0; u < 16; u++) { A[u] = 0.0f; B[u] = 0.0f; }

#pragma unroll
    for (int kwv = 0; kwv < 16; kwv++) {
        float2 z = Zs[r * 16 + kwv];
#pragma unroll
        for (int u4 = 0; u4 < 4; u4++) {
            float4 c4 = *(const float4*)&Ct[kwv * 128 + wb * 16 + u4 * 4];
            float4 s4 = *(const float4*)&St[kwv * 128 + wb * 16 + u4 * 4];
            float* T = ((kwv & 1) == 0) ? A : B;
            T[u4 * 4 + 0] += z.x * c4.x - z.y * s4.x;
            T[u4 * 4 + 1] += z.x * c4.y - z.y * s4.y;
            T[u4 * 4 + 2] += z.x * c4.z - z.y * s4.z;
            T[u4 * 4 + 3] += z.x * c4.w - z.y * s4.w;
        }
    }

    float* orow = out + (size_t)blockIdx.x * (32 * 256) + r * 256 + wb * 16;
#pragma unroll
    for (int u4 = 0; u4 < 4; u4++) {
        float4 lo = make_float4(A[u4*4+0] + B[u4*4+0], A[u4*4+1] + B[u4*4+1],
                                A[u4*4+2] + B[u4*4+2], A[u4*4+3] + B[u4*4+3]);
        float4 hi = make_float4(A[u4*4+0] - B[u4*4+0], A[u4*4+1] - B[u4*4+1],
                                A[u4*4+2] - B[u4*4+2], A[u4*4+3] - B[u4*4+3]);
        *(float4*)&orow[u4 * 4]       = lo;
        *(float4*)&orow[128 + u4 * 4] = hi;
    }
}

// ---------------------------------------------------------------------------
extern "C" void kernel_launch(void* const* d_in, const int* in_sizes, int n_in,
                              void* d_out, int out_size) {
    const float* t = nullptr;
    const float* x = nullptr;
    const float* w[4] = {nullptr, nullptr, nullptr, nullptr};
    int wn = 0;
    for (int i = 0; i < n_in; i++) {
        if (in_sizes[i] == BB * TD)                      t = (const float*)d_in[i];
        else if (in_sizes[i] == BB * IC * NV * HH * WW)  x = (const float*)d_in[i];
        else if (wn < 4)                                 w[wn++] = (const float*)d_in[i];
    }
    float* out = (float*)d_out;

    k0_tables<<<8, 256>>>();
    k1_fwd_w<<<6144, 128>>>(x);
    k2_fwd_h<<<384, 256>>>();
    k3a_time<<<dim3(96, 4), 128>>>(t, w[0], w[1], w[2], w[3]);
    k3b_mix<<<768, 256>>>();
    k4_inv_h<<<384, 128>>>();
    k5_inv_w<<<3072, 256>>>(out);
}